// round 5
// baseline (speedup 1.0000x reference)
#include <cuda_runtime.h>
#include <cuda_fp16.h>
#include <math.h>

#define NF   40
#define DD   64
#define AA   32
#define PPV  780      // valid pairs
#define NTH  256      // threads per CTA (8 warps)
#define NW   8
#define TR   128      // pair-tile rows (8 warps x 16)
#define NTILE 7
#define PADP (TR * NTILE)   // 896
#define NT   4        // n8 tiles (32 attn cols)
#define XS   68       // sx row stride (floats), 16B aligned

// permuted k location: one float4 at (tig*16 + blk*4) holds the thread's
// m16n8k16 A-fragment k-values {16blk+2tig, +1, 16blk+2tig+8, +9}
__device__ __forceinline__ int kloc(int k) {
    return (((k >> 1) & 3) << 4) | ((k >> 4) << 2) | (((k >> 3) & 1) << 1) | (k & 1);
}

__device__ __forceinline__ unsigned h2(float lo, float hi) {
    __half2 h = __floats2half2_rn(lo, hi);
    return *reinterpret_cast<unsigned*>(&h);
}

__device__ __forceinline__ void mma_f16(float c[4],
                                        unsigned a0, unsigned a1, unsigned a2, unsigned a3,
                                        unsigned b0, unsigned b1) {
    asm("mma.sync.aligned.m16n8k16.row.col.f32.f16.f16.f32 "
        "{%0,%1,%2,%3}, {%4,%5,%6,%7}, {%8,%9}, {%0,%1,%2,%3};"
        : "+f"(c[0]), "+f"(c[1]), "+f"(c[2]), "+f"(c[3])
        : "r"(a0), "r"(a1), "r"(a2), "r"(a3), "r"(b0), "r"(b1));
}

__global__ __launch_bounds__(NTH, 2)
void afm_kernel(const float* __restrict__ x,
                const float* __restrict__ W1,
                const float* __restrict__ b1,
                const float* __restrict__ w2,
                const float* __restrict__ pvec,
                float* __restrict__ out)
{
    __shared__ float sx[NF * XS];       // k-permuted x
    __shared__ float sW[DD * AA];       // W1 [k][n] fp32 (prologue only)
    __shared__ float spp[DD];           // k-permuted p
    __shared__ float sb1[AA], sw2[AA];
    __shared__ int   spi[PADP], spj[PADP];
    __shared__ float slog[PPV], ssv[PPV];
    __shared__ float red[32];

    const int b    = blockIdx.x;
    const int tid  = threadIdx.x;
    const int lane = tid & 31;
    const int wrp  = tid >> 5;
    const int gid  = lane >> 2;   // 0..7
    const int tig  = lane & 3;    // 0..3

    // ---- stage permuted x ----
    const float* xb = x + (size_t)b * (NF * DD);
    for (int t = tid; t < NF * DD; t += NTH) {
        int f = t >> 6, k = t & 63;
        sx[f * XS + kloc(k)] = xb[t];
    }
    for (int t = tid; t < DD * AA; t += NTH) sW[t] = W1[t];
    if (tid < DD) spp[kloc(tid)] = pvec[tid];
    if (tid < AA) { sb1[tid] = b1[tid]; sw2[tid] = w2[tid]; }
    // ---- pair tables ----
    for (int pp = tid; pp < PADP; pp += NTH) {
        int i = 0, j = 0;
        if (pp < PPV) {
            int rem = pp, span = NF - 1;
            while (rem >= span) { rem -= span; i++; span--; }
            j = i + 1 + rem;
        }
        spi[pp] = i; spj[pp] = j;
    }
    __syncthreads();

    // ---- B fragments in half2 regs: Bh[blk][n][0..1], 32 regs ----
    unsigned Bh[4][NT][2];
    #pragma unroll
    for (int blk = 0; blk < 4; blk++) {
        const int k0 = blk * 16 + 2 * tig;
        #pragma unroll
        for (int n = 0; n < NT; n++) {
            const int col = n * 8 + gid;
            Bh[blk][n][0] = h2(sW[k0 * AA + col],       sW[(k0 + 1) * AA + col]);
            Bh[blk][n][1] = h2(sW[(k0 + 8) * AA + col], sW[(k0 + 9) * AA + col]);
        }
    }
    // ---- p fragments (loop-invariant), 4 float4 = 16 regs ----
    const float4* spp4 = (const float4*)spp;
    float4 pv[4];
    #pragma unroll
    for (int blk = 0; blk < 4; blk++) pv[blk] = spp4[tig * 4 + blk];

    const int row0 = wrp * 16 + gid;

    // ---- 7 tiles of 128 pairs; no smem prod, no intra-loop barriers ----
    #pragma unroll 1
    for (int t = 0; t < NTILE; t++) {
        const int pA = t * TR + row0;
        const float4* xi0 = (const float4*)(sx + spi[pA] * XS);
        const float4* xj0 = (const float4*)(sx + spj[pA] * XS);
        const float4* xi1 = (const float4*)(sx + spi[pA + 8] * XS);
        const float4* xj1 = (const float4*)(sx + spj[pA + 8] * XS);

        float acc[NT][4];
        #pragma unroll
        for (int n = 0; n < NT; n++)
            { acc[n][0] = acc[n][1] = acc[n][2] = acc[n][3] = 0.0f; }
        float s0 = 0.0f, s1 = 0.0f;

        #pragma unroll
        for (int blk = 0; blk < 4; blk++) {
            const int c = tig * 4 + blk;
            float4 vi0 = xi0[c], vj0 = xj0[c];
            float4 vi1 = xi1[c], vj1 = xj1[c];

            float p00 = vi0.x * vj0.x, p01 = vi0.y * vj0.y;
            float p02 = vi0.z * vj0.z, p03 = vi0.w * vj0.w;
            float p10 = vi1.x * vj1.x, p11 = vi1.y * vj1.y;
            float p12 = vi1.z * vj1.z, p13 = vi1.w * vj1.w;

            s0 = fmaf(p00, pv[blk].x, fmaf(p01, pv[blk].y,
                 fmaf(p02, pv[blk].z, fmaf(p03, pv[blk].w, s0))));
            s1 = fmaf(p10, pv[blk].x, fmaf(p11, pv[blk].y,
                 fmaf(p12, pv[blk].z, fmaf(p13, pv[blk].w, s1))));

            unsigned a0 = h2(p00, p01), a2 = h2(p02, p03);
            unsigned a1 = h2(p10, p11), a3 = h2(p12, p13);
            #pragma unroll
            for (int n = 0; n < NT; n++)
                mma_f16(acc[n], a0, a1, a2, a3, Bh[blk][n][0], Bh[blk][n][1]);
        }

        // epilogue: logit = sum_n relu(acc + b1)*w2 (cols n*8+2tig, +1)
        float ls0 = 0.0f, ls1 = 0.0f;
        #pragma unroll
        for (int n = 0; n < NT; n++) {
            float bb0 = sb1[n * 8 + 2 * tig], bb1 = sb1[n * 8 + 2 * tig + 1];
            float ww0 = sw2[n * 8 + 2 * tig], ww1 = sw2[n * 8 + 2 * tig + 1];
            ls0 += fmaxf(acc[n][0] + bb0, 0.0f) * ww0
                 + fmaxf(acc[n][1] + bb1, 0.0f) * ww1;
            ls1 += fmaxf(acc[n][2] + bb0, 0.0f) * ww0
                 + fmaxf(acc[n][3] + bb1, 0.0f) * ww1;
        }
        ls0 += __shfl_xor_sync(0xFFFFFFFFu, ls0, 1);
        ls0 += __shfl_xor_sync(0xFFFFFFFFu, ls0, 2);
        ls1 += __shfl_xor_sync(0xFFFFFFFFu, ls1, 1);
        ls1 += __shfl_xor_sync(0xFFFFFFFFu, ls1, 2);
        s0  += __shfl_xor_sync(0xFFFFFFFFu, s0, 1);
        s0  += __shfl_xor_sync(0xFFFFFFFFu, s0, 2);
        s1  += __shfl_xor_sync(0xFFFFFFFFu, s1, 1);
        s1  += __shfl_xor_sync(0xFFFFFFFFu, s1, 2);
        if (tig == 0) {
            if (pA < PPV)     { slog[pA] = ls0;     ssv[pA] = s0; }
            if (pA + 8 < PPV) { slog[pA + 8] = ls1; ssv[pA + 8] = s1; }
        }
    }
    __syncthreads();

    // ---- softmax over 780 pairs + weighted sum ----
    float lmax = -INFINITY;
    for (int pp = tid; pp < PPV; pp += NTH) lmax = fmaxf(lmax, slog[pp]);
    #pragma unroll
    for (int o = 16; o > 0; o >>= 1)
        lmax = fmaxf(lmax, __shfl_xor_sync(0xFFFFFFFFu, lmax, o));
    if (lane == 0) red[wrp] = lmax;
    __syncthreads();
    if (tid == 0) {
        float m = red[0];
        #pragma unroll
        for (int w = 1; w < NW; w++) m = fmaxf(m, red[w]);
        red[16] = m;
    }
    __syncthreads();
    const float mx = red[16];

    float num = 0.0f, den = 0.0f;
    for (int pp = tid; pp < PPV; pp += NTH) {
        float e = __expf(slog[pp] - mx);
        num = fmaf(e, ssv[pp], num);
        den += e;
    }
    #pragma unroll
    for (int o = 16; o > 0; o >>= 1) {
        num += __shfl_xor_sync(0xFFFFFFFFu, num, o);
        den += __shfl_xor_sync(0xFFFFFFFFu, den, o);
    }
    __syncthreads();
    if (lane == 0) { red[wrp] = num; red[8 + wrp] = den; }
    __syncthreads();
    if (tid == 0) {
        float n = 0.0f, d = 0.0f;
        #pragma unroll
        for (int w = 0; w < NW; w++) { n += red[w]; d += red[8 + w]; }
        out[b] = n / d;
    }
}

extern "C" void kernel_launch(void* const* d_in, const int* in_sizes, int n_in,
                              void* d_out, int out_size)
{
    const float* x    = (const float*)d_in[0];
    const float* W1   = (const float*)d_in[1];
    const float* b1   = (const float*)d_in[2];
    const float* w2   = (const float*)d_in[3];
    const float* pvec = (const float*)d_in[4];
    float* out = (float*)d_out;

    int B = in_sizes[0] / (NF * DD);
    afm_kernel<<<B, NTH>>>(x, W1, b1, w2, pvec, out);
}

// round 9
// speedup vs baseline: 1.2546x; 1.2546x over previous
#include <cuda_runtime.h>
#include <cuda_fp16.h>
#include <math.h>

#define NF   40
#define DD   64
#define AA   32
#define NROW 48          // padded M rows (3 m16 tiles)
#define NCOL 40          // N (5 n8 tiles)
#define NTL  5
#define NTH  192         // 6 warps
#define NW   6
#define XS   68          // sx row stride (floats), 17 float4
#define NA   33          // 32 attn cols + p

// permuted k location: float4 at (tig*16 + kb*4) of a row holds k-values
// {16kb+2tig, 16kb+2tig+1, 16kb+2tig+8, 16kb+2tig+9}
__device__ __forceinline__ int kloc(int k) {
    return (((k >> 1) & 3) << 4) | ((k >> 4) << 2) | (((k >> 3) & 1) << 1) | (k & 1);
}

__device__ __forceinline__ unsigned h2(float lo, float hi) {
    __half2 h = __floats2half2_rn(lo, hi);
    return *reinterpret_cast<unsigned*>(&h);
}
__device__ __forceinline__ unsigned hmul2u(unsigned a, unsigned b) {
    __half2 r = __hmul2(*reinterpret_cast<__half2*>(&a), *reinterpret_cast<__half2*>(&b));
    return *reinterpret_cast<unsigned*>(&r);
}

__device__ __forceinline__ void mma_f16(float c[4],
                                        unsigned a0, unsigned a1, unsigned a2, unsigned a3,
                                        unsigned b0, unsigned b1) {
    asm("mma.sync.aligned.m16n8k16.row.col.f32.f16.f16.f32 "
        "{%0,%1,%2,%3}, {%4,%5,%6,%7}, {%8,%9}, {%0,%1,%2,%3};"
        : "+f"(c[0]), "+f"(c[1]), "+f"(c[2]), "+f"(c[3])
        : "r"(a0), "r"(a1), "r"(a2), "r"(a3), "r"(b0), "r"(b1));
}

__global__ __launch_bounds__(NTH, 2)
void afm_kernel(const float* __restrict__ x,
                const float* __restrict__ W1,
                const float* __restrict__ b1,
                const float* __restrict__ w2,
                const float* __restrict__ pvec,
                float* __restrict__ out)
{
    __shared__ __align__(16) float sx[NROW * XS];   // k-permuted X, zero-padded rows
    __shared__ uint2 sWh[NA * 16];   // scale half2 pairs: [(a*4+kb)*4 + tig]
    __shared__ float sb1[AA], sw2[AA];
    __shared__ float sL0[NROW * NCOL];   // partial logits, a-group 0
    __shared__ float sL1[NROW * NCOL];   // partial logits, a-group 1
    __shared__ float sS [NROW * NCOL];   // s matrix (prod . p)
    __shared__ float red[32];

    const int b    = blockIdx.x;
    const int tid  = threadIdx.x;
    const int lane = tid & 31;
    const int wrp  = tid >> 5;
    const int gid  = lane >> 2;   // 0..7
    const int tig  = lane & 3;    // 0..3
    const int mt   = wrp % 3;     // m-tile
    const int ag   = wrp / 3;     // a-group

    // ---- stage permuted X (rows >= 40 zeroed) ----
    const float* xb = x + (size_t)b * (NF * DD);
    for (int t = tid; t < NROW * DD; t += NTH) {
        int f = t >> 6, k = t & 63;
        sx[f * XS + kloc(k)] = (f < NF) ? xb[f * DD + k] : 0.0f;
    }
    // ---- stage scale half2 pairs: a<32 -> W1 col, a==32 -> p ----
    for (int t = tid; t < NA * 16; t += NTH) {
        int a = t >> 4, r = t & 15, kb = r >> 2, tg = r & 3;
        int k0 = kb * 16 + 2 * tg;
        float w0, w1, w8, w9;
        if (a < AA) {
            w0 = W1[k0 * AA + a];       w1 = W1[(k0 + 1) * AA + a];
            w8 = W1[(k0 + 8) * AA + a]; w9 = W1[(k0 + 9) * AA + a];
        } else {
            w0 = pvec[k0];     w1 = pvec[k0 + 1];
            w8 = pvec[k0 + 8]; w9 = pvec[k0 + 9];
        }
        sWh[t] = make_uint2(h2(w0, w1), h2(w8, w9));
    }
    if (tid < AA) { sb1[tid] = b1[tid]; sw2[tid] = w2[tid]; }
    __syncthreads();

    // ---- load A / B fragments of X once (register-resident) ----
    const float4* sx4 = (const float4*)sx;     // row stride 17 float4
    const int r0 = mt * 16 + gid, r1 = r0 + 8;
    unsigned Ax[4][4];
    #pragma unroll
    for (int kb = 0; kb < 4; kb++) {
        float4 v0 = sx4[r0 * 17 + tig * 4 + kb];
        float4 v1 = sx4[r1 * 17 + tig * 4 + kb];
        Ax[kb][0] = h2(v0.x, v0.y);  Ax[kb][2] = h2(v0.z, v0.w);
        Ax[kb][1] = h2(v1.x, v1.y);  Ax[kb][3] = h2(v1.z, v1.w);
    }
    unsigned Bx[NTL][4][2];
    #pragma unroll
    for (int nt = 0; nt < NTL; nt++) {
        const int rb = nt * 8 + gid;
        #pragma unroll
        for (int kb = 0; kb < 4; kb++) {
            float4 v = sx4[rb * 17 + tig * 4 + kb];
            Bx[nt][kb][0] = h2(v.x, v.y);
            Bx[nt][kb][1] = h2(v.z, v.w);
        }
    }

    // ---- a-loop: G_a = (X diag(w_a)) X^T, accumulate logits in-register ----
    float logit[NTL][4];
    #pragma unroll
    for (int nt = 0; nt < NTL; nt++)
        { logit[nt][0] = logit[nt][1] = logit[nt][2] = logit[nt][3] = 0.0f; }

    #pragma unroll 1
    for (int ai = 0; ai < 16; ai++) {
        const int a = ag * 16 + ai;
        float G[NTL][4];
        #pragma unroll
        for (int nt = 0; nt < NTL; nt++)
            { G[nt][0] = G[nt][1] = G[nt][2] = G[nt][3] = 0.0f; }
        #pragma unroll
        for (int kb = 0; kb < 4; kb++) {
            uint2 sc = sWh[(a * 4 + kb) * 4 + tig];
            unsigned y0 = hmul2u(Ax[kb][0], sc.x);
            unsigned y1 = hmul2u(Ax[kb][1], sc.x);
            unsigned y2 = hmul2u(Ax[kb][2], sc.y);
            unsigned y3 = hmul2u(Ax[kb][3], sc.y);
            #pragma unroll
            for (int nt = 0; nt < NTL; nt++)
                mma_f16(G[nt], y0, y1, y2, y3, Bx[nt][kb][0], Bx[nt][kb][1]);
        }
        const float bba = sb1[a], wwa = sw2[a];
        #pragma unroll
        for (int nt = 0; nt < NTL; nt++)
            #pragma unroll
            for (int q = 0; q < 4; q++)
                logit[nt][q] = fmaf(fmaxf(G[nt][q] + bba, 0.0f), wwa, logit[nt][q]);
    }

    // ---- p pass (a-group 0 only): s = x_i^T diag(p) x_j -> sS ----
    if (ag == 0) {
        float G[NTL][4];
        #pragma unroll
        for (int nt = 0; nt < NTL; nt++)
            { G[nt][0] = G[nt][1] = G[nt][2] = G[nt][3] = 0.0f; }
        #pragma unroll
        for (int kb = 0; kb < 4; kb++) {
            uint2 sc = sWh[(AA * 4 + kb) * 4 + tig];
            unsigned y0 = hmul2u(Ax[kb][0], sc.x);
            unsigned y1 = hmul2u(Ax[kb][1], sc.x);
            unsigned y2 = hmul2u(Ax[kb][2], sc.y);
            unsigned y3 = hmul2u(Ax[kb][3], sc.y);
            #pragma unroll
            for (int nt = 0; nt < NTL; nt++)
                mma_f16(G[nt], y0, y1, y2, y3, Bx[nt][kb][0], Bx[nt][kb][1]);
        }
        #pragma unroll
        for (int nt = 0; nt < NTL; nt++) {
            const int j0 = nt * 8 + 2 * tig;
            sS[r0 * NCOL + j0]     = G[nt][0];
            sS[r0 * NCOL + j0 + 1] = G[nt][1];
            sS[r1 * NCOL + j0]     = G[nt][2];
            sS[r1 * NCOL + j0 + 1] = G[nt][3];
        }
    }

    // ---- write partial logits ----
    {
        float* dst = ag ? sL1 : sL0;
        #pragma unroll
        for (int nt = 0; nt < NTL; nt++) {
            const int j0 = nt * 8 + 2 * tig;
            dst[r0 * NCOL + j0]     = logit[nt][0];
            dst[r0 * NCOL + j0 + 1] = logit[nt][1];
            dst[r1 * NCOL + j0]     = logit[nt][2];
            dst[r1 * NCOL + j0 + 1] = logit[nt][3];
        }
    }
    __syncthreads();

    // ---- masked softmax over strict upper triangle (j > i) + weighted sum ----
    float lmax = -INFINITY;
    for (int t = tid; t < NF * NCOL; t += NTH) {
        int i = t / NCOL, j = t - i * NCOL;
        if (j > i) lmax = fmaxf(lmax, sL0[t] + sL1[t]);
    }
    #pragma unroll
    for (int o = 16; o > 0; o >>= 1)
        lmax = fmaxf(lmax, __shfl_xor_sync(0xFFFFFFFFu, lmax, o));
    if (lane == 0) red[wrp] = lmax;
    __syncthreads();
    if (tid == 0) {
        float m = red[0];
        #pragma unroll
        for (int w = 1; w < NW; w++) m = fmaxf(m, red[w]);
        red[16] = m;
    }
    __syncthreads();
    const float mx = red[16];

    float num = 0.0f, den = 0.0f;
    for (int t = tid; t < NF * NCOL; t += NTH) {
        int i = t / NCOL, j = t - i * NCOL;
        if (j > i) {
            float e = __expf(sL0[t] + sL1[t] - mx);
            num = fmaf(e, sS[t], num);
            den += e;
        }
    }
    #pragma unroll
    for (int o = 16; o > 0; o >>= 1) {
        num += __shfl_xor_sync(0xFFFFFFFFu, num, o);
        den += __shfl_xor_sync(0xFFFFFFFFu, den, o);
    }
    __syncthreads();
    if (lane == 0) { red[wrp] = num; red[8 + wrp] = den; }
    __syncthreads();
    if (tid == 0) {
        float n = 0.0f, d = 0.0f;
        #pragma unroll
        for (int w = 0; w < NW; w++) { n += red[w]; d += red[8 + w]; }
        out[b] = n / d;
    }
}

extern "C" void kernel_launch(void* const* d_in, const int* in_sizes, int n_in,
                              void* d_out, int out_size)
{
    const float* x    = (const float*)d_in[0];
    const float* W1   = (const float*)d_in[1];
    const float* b1   = (const float*)d_in[2];
    const float* w2   = (const float*)d_in[3];
    const float* pvec = (const float*)d_in[4];
    float* out = (float*)d_out;

    int B = in_sizes[0] / (NF * DD);
    afm_kernel<<<B, NTH>>>(x, W1, b1, w2, pvec, out);
}

// round 10
// speedup vs baseline: 1.6598x; 1.3229x over previous
#include <cuda_runtime.h>
#include <cuda_fp16.h>
#include <math.h>

#define NF   40
#define DD   64
#define AA   32
#define NROW 48          // padded M rows (3 m16 tiles)
#define NCOL 40          // N (5 n8 tiles)
#define NTH  192         // 6 warps
#define NW   6
#define XS   68          // sx row stride (floats), 17 float4
#define NA   33          // 32 attn cols + p

// permuted k location: float4 at (tig*16 + kb*4) of a row holds k-values
// {16kb+2tig, 16kb+2tig+1, 16kb+2tig+8, 16kb+2tig+9}
__device__ __forceinline__ int kloc(int k) {
    return (((k >> 1) & 3) << 4) | ((k >> 4) << 2) | (((k >> 3) & 1) << 1) | (k & 1);
}

__device__ __forceinline__ unsigned h2(float lo, float hi) {
    __half2 h = __floats2half2_rn(lo, hi);
    return *reinterpret_cast<unsigned*>(&h);
}
__device__ __forceinline__ unsigned hmul2u(unsigned a, unsigned b) {
    __half2 r = __hmul2(*reinterpret_cast<__half2*>(&a), *reinterpret_cast<__half2*>(&b));
    return *reinterpret_cast<unsigned*>(&r);
}

__device__ __forceinline__ void mma_f16(float c[4],
                                        unsigned a0, unsigned a1, unsigned a2, unsigned a3,
                                        unsigned b0, unsigned b1) {
    asm("mma.sync.aligned.m16n8k16.row.col.f32.f16.f16.f32 "
        "{%0,%1,%2,%3}, {%4,%5,%6,%7}, {%8,%9}, {%0,%1,%2,%3};"
        : "+f"(c[0]), "+f"(c[1]), "+f"(c[2]), "+f"(c[3])
        : "r"(a0), "r"(a1), "r"(a2), "r"(a3), "r"(b0), "r"(b1));
}

__global__ __launch_bounds__(NTH, 3)
void afm_kernel(const float* __restrict__ x,
                const float* __restrict__ W1,
                const float* __restrict__ b1,
                const float* __restrict__ w2,
                const float* __restrict__ pvec,
                float* __restrict__ out)
{
    __shared__ __align__(16) float sx[NROW * XS];   // k-permuted X, zero-padded rows
    __shared__ uint2 sWh[NA * 16];   // scale half2 pairs: [(a*4+kb)*4 + tig]
    __shared__ float sb1[AA], sw2[AA];
    __shared__ float sL0[NROW * NCOL];   // partial logits, a-group 0
    __shared__ float sL1[NROW * NCOL];   // partial logits, a-group 1
    __shared__ float sS [NROW * NCOL];   // s matrix (prod . p)
    __shared__ float red[32];

    const int b    = blockIdx.x;
    const int tid  = threadIdx.x;
    const int lane = tid & 31;
    const int wrp  = tid >> 5;
    const int gid  = lane >> 2;   // 0..7
    const int tig  = lane & 3;    // 0..3
    const int wg   = wrp % 3;     // tile-set id
    const int ag   = wrp / 3;     // a-group

    // tile lists: warp wg computes tiles (mA[aSel[t]], nb[t]), t=0..2, aSel={0,0,1}
    // wg0: (0,0)(0,1)(0,2)  wg1: (0,3)(0,4)(1,2)  wg2: (1,3)(1,4)(2,4)
    const int mA0 = (wg == 2) ? 1 : 0;
    const int mA1 = wg;
    const int nb0 = (wg == 0) ? 0 : 3;
    const int nb1 = (wg == 0) ? 1 : 4;
    const int nb2 = (wg == 0) ? 2 : ((wg == 1) ? 2 : 4);

    // ---- stage permuted X (rows >= 40 zeroed) ----
    const float* xb = x + (size_t)b * (NF * DD);
    for (int t = tid; t < NROW * DD; t += NTH) {
        int f = t >> 6, k = t & 63;
        sx[f * XS + kloc(k)] = (f < NF) ? xb[f * DD + k] : 0.0f;
    }
    // ---- stage scale half2 pairs: a<32 -> W1 col, a==32 -> p ----
    for (int t = tid; t < NA * 16; t += NTH) {
        int a = t >> 4, r = t & 15, kb = r >> 2, tg = r & 3;
        int k0 = kb * 16 + 2 * tg;
        float w0, w1, w8, w9;
        if (a < AA) {
            w0 = W1[k0 * AA + a];       w1 = W1[(k0 + 1) * AA + a];
            w8 = W1[(k0 + 8) * AA + a]; w9 = W1[(k0 + 9) * AA + a];
        } else {
            w0 = pvec[k0];     w1 = pvec[k0 + 1];
            w8 = pvec[k0 + 8]; w9 = pvec[k0 + 9];
        }
        sWh[t] = make_uint2(h2(w0, w1), h2(w8, w9));
    }
    if (tid < AA) { sb1[tid] = b1[tid]; sw2[tid] = w2[tid]; }
    __syncthreads();

    // ---- load this warp's A / B fragments of X once (register-resident) ----
    const float4* sx4 = (const float4*)sx;     // row stride 17 float4
    unsigned Ax[2][4][4];
    #pragma unroll
    for (int s = 0; s < 2; s++) {
        const int rr = (s ? mA1 : mA0) * 16 + gid;
        #pragma unroll
        for (int kb = 0; kb < 4; kb++) {
            float4 v0 = sx4[rr * 17 + tig * 4 + kb];
            float4 v1 = sx4[(rr + 8) * 17 + tig * 4 + kb];
            Ax[s][kb][0] = h2(v0.x, v0.y);  Ax[s][kb][2] = h2(v0.z, v0.w);
            Ax[s][kb][1] = h2(v1.x, v1.y);  Ax[s][kb][3] = h2(v1.z, v1.w);
        }
    }
    unsigned Bx[3][4][2];
    #pragma unroll
    for (int t = 0; t < 3; t++) {
        const int rb = ((t == 0) ? nb0 : (t == 1) ? nb1 : nb2) * 8 + gid;
        #pragma unroll
        for (int kb = 0; kb < 4; kb++) {
            float4 v = sx4[rb * 17 + tig * 4 + kb];
            Bx[t][kb][0] = h2(v.x, v.y);
            Bx[t][kb][1] = h2(v.z, v.w);
        }
    }

    // ---- a-loop: 3 tiles of G_a, scale applied to B side ----
    float logit[3][4];
    #pragma unroll
    for (int t = 0; t < 3; t++)
        { logit[t][0] = logit[t][1] = logit[t][2] = logit[t][3] = 0.0f; }

    #pragma unroll 1
    for (int ai = 0; ai < 16; ai++) {
        const int a = ag * 16 + ai;
        uint2 sc[4];
        #pragma unroll
        for (int kb = 0; kb < 4; kb++) sc[kb] = sWh[(a * 4 + kb) * 4 + tig];

        float G[3][4];
        #pragma unroll
        for (int t = 0; t < 3; t++)
            { G[t][0] = G[t][1] = G[t][2] = G[t][3] = 0.0f; }
        #pragma unroll
        for (int kb = 0; kb < 4; kb++) {
            #pragma unroll
            for (int t = 0; t < 3; t++) {
                unsigned z0 = hmul2u(Bx[t][kb][0], sc[kb].x);
                unsigned z1 = hmul2u(Bx[t][kb][1], sc[kb].y);
                const int s = (t == 2) ? 1 : 0;
                mma_f16(G[t], Ax[s][kb][0], Ax[s][kb][1], Ax[s][kb][2], Ax[s][kb][3], z0, z1);
            }
        }
        const float bba = sb1[a], wwa = sw2[a];
        #pragma unroll
        for (int t = 0; t < 3; t++)
            #pragma unroll
            for (int q = 0; q < 4; q++)
                logit[t][q] = fmaf(fmaxf(G[t][q] + bba, 0.0f), wwa, logit[t][q]);
    }

    // ---- p pass (a-group 0 only): s = x_i^T diag(p) x_j -> sS ----
    if (ag == 0) {
        uint2 sc[4];
        #pragma unroll
        for (int kb = 0; kb < 4; kb++) sc[kb] = sWh[(AA * 4 + kb) * 4 + tig];
        float G[3][4];
        #pragma unroll
        for (int t = 0; t < 3; t++)
            { G[t][0] = G[t][1] = G[t][2] = G[t][3] = 0.0f; }
        #pragma unroll
        for (int kb = 0; kb < 4; kb++) {
            #pragma unroll
            for (int t = 0; t < 3; t++) {
                unsigned z0 = hmul2u(Bx[t][kb][0], sc[kb].x);
                unsigned z1 = hmul2u(Bx[t][kb][1], sc[kb].y);
                const int s = (t == 2) ? 1 : 0;
                mma_f16(G[t], Ax[s][kb][0], Ax[s][kb][1], Ax[s][kb][2], Ax[s][kb][3], z0, z1);
            }
        }
        #pragma unroll
        for (int t = 0; t < 3; t++) {
            const int mt = (t == 2) ? mA1 : mA0;
            const int nt = (t == 0) ? nb0 : (t == 1) ? nb1 : nb2;
            const int m0 = mt * 16 + gid, j0 = nt * 8 + 2 * tig;
            sS[m0 * NCOL + j0]           = G[t][0];
            sS[m0 * NCOL + j0 + 1]       = G[t][1];
            sS[(m0 + 8) * NCOL + j0]     = G[t][2];
            sS[(m0 + 8) * NCOL + j0 + 1] = G[t][3];
        }
    }

    // ---- write partial logits ----
    {
        float* dst = ag ? sL1 : sL0;
        #pragma unroll
        for (int t = 0; t < 3; t++) {
            const int mt = (t == 2) ? mA1 : mA0;
            const int nt = (t == 0) ? nb0 : (t == 1) ? nb1 : nb2;
            const int m0 = mt * 16 + gid, j0 = nt * 8 + 2 * tig;
            dst[m0 * NCOL + j0]           = logit[t][0];
            dst[m0 * NCOL + j0 + 1]       = logit[t][1];
            dst[(m0 + 8) * NCOL + j0]     = logit[t][2];
            dst[(m0 + 8) * NCOL + j0 + 1] = logit[t][3];
        }
    }
    __syncthreads();

    // ---- masked softmax over strict upper triangle (j > i) + weighted sum ----
    float lmax = -INFINITY;
    for (int t = tid; t < NF * NCOL; t += NTH) {
        int i = t / NCOL, j = t - i * NCOL;
        if (j > i) lmax = fmaxf(lmax, sL0[t] + sL1[t]);
    }
    #pragma unroll
    for (int o = 16; o > 0; o >>= 1)
        lmax = fmaxf(lmax, __shfl_xor_sync(0xFFFFFFFFu, lmax, o));
    if (lane == 0) red[wrp] = lmax;
    __syncthreads();
    if (tid == 0) {
        float m = red[0];
        #pragma unroll
        for (int w = 1; w < NW; w++) m = fmaxf(m, red[w]);
        red[16] = m;
    }
    __syncthreads();
    const float mx = red[16];

    float num = 0.0f, den = 0.0f;
    for (int t = tid; t < NF * NCOL; t += NTH) {
        int i = t / NCOL, j = t - i * NCOL;
        if (j > i) {
            float e = __expf(sL0[t] + sL1[t] - mx);
            num = fmaf(e, sS[t], num);
            den += e;
        }
    }
    #pragma unroll
    for (int o = 16; o > 0; o >>= 1) {
        num += __shfl_xor_sync(0xFFFFFFFFu, num, o);
        den += __shfl_xor_sync(0xFFFFFFFFu, den, o);
    }
    __syncthreads();
    if (lane == 0) { red[wrp] = num; red[8 + wrp] = den; }
    __syncthreads();
    if (tid == 0) {
        float n = 0.0f, d = 0.0f;
        #pragma unroll
        for (int w = 0; w < NW; w++) { n += red[w]; d += red[8 + w]; }
        out[b] = n / d;
    }
}

extern "C" void kernel_launch(void* const* d_in, const int* in_sizes, int n_in,
                              void* d_out, int out_size)
{
    const float* x    = (const float*)d_in[0];
    const float* W1   = (const float*)d_in[1];
    const float* b1   = (const float*)d_in[2];
    const float* w2   = (const float*)d_in[3];
    const float* pvec = (const float*)d_in[4];
    float* out = (float*)d_out;

    int B = in_sizes[0] / (NF * DD);
    afm_kernel<<<B, NTH>>>(x, W1, b1, w2, pvec, out);
}